// round 16
// baseline (speedup 1.0000x reference)
#include <cuda_runtime.h>
#include <cuda_bf16.h>
#include <cuda_fp16.h>
#include <cstdint>

#define BB 8
#define KN 512
#define QN 128
#define DD 256
#define NEGC (-1000000.0f)

#define BM 64
#define BN 64
#define BK 32

// scratch
__device__ __half g_qproj[BB * QN * DD];                 // [b*128+q][h]     512KB
__device__ __half g_kprojT[BB * (DD / 8) * KN * 8];      // [b][h/8][k][h%8]   2MB

__device__ __forceinline__ unsigned int htanh2(unsigned int x) {
    unsigned int y;
    asm("tanh.approx.f16x2 %0, %1;" : "=r"(y) : "r"(x));
    return y;
}
__device__ __forceinline__ unsigned int hadd2u(unsigned int a, unsigned int b) {
    unsigned int r;
    asm("add.f16x2 %0, %1, %2;" : "=r"(r) : "r"(a), "r"(b));
    return r;
}
__device__ __forceinline__ unsigned int hfma2u(unsigned int a, unsigned int b, unsigned int c) {
    unsigned int r;
    asm("fma.rn.f16x2 %0, %1, %2, %3;" : "=r"(r) : "r"(a), "r"(b), "r"(c));
    return r;
}
__device__ __forceinline__ unsigned int packf2(float2 v) {
    __half2 h = __floats2half2_rn(v.x, v.y);
    return *(unsigned int*)&h;
}
__device__ __forceinline__ void mma16816(float c[4],
    unsigned int a0, unsigned int a1, unsigned int a2, unsigned int a3,
    unsigned int b0, unsigned int b1)
{
    asm("mma.sync.aligned.m16n8k16.row.col.f32.f16.f16.f32 "
        "{%0,%1,%2,%3}, {%4,%5,%6,%7}, {%8,%9}, {%0,%1,%2,%3};"
        : "+f"(c[0]), "+f"(c[1]), "+f"(c[2]), "+f"(c[3])
        : "r"(a0), "r"(a1), "r"(a2), "r"(a3), "r"(b0), "r"(b1));
}
__device__ __forceinline__ void ldsm4(unsigned int& r0, unsigned int& r1,
                                      unsigned int& r2, unsigned int& r3,
                                      unsigned int addr)
{
    asm volatile("ldmatrix.sync.aligned.m8n8.x4.shared.b16 {%0,%1,%2,%3}, [%4];"
        : "=r"(r0), "=r"(r1), "=r"(r2), "=r"(r3) : "r"(addr));
}

// ---------------------------------------------------------------------------
// Kernel 1: projection GEMM, smem-staged tensor-core pipeline. (unchanged)
// ---------------------------------------------------------------------------
__global__ __launch_bounds__(256) void proj_kernel(
    const float* __restrict__ queries,
    const float* __restrict__ keys,
    const float* __restrict__ W_hidden)
{
    __shared__ __half sA[2][BM][40];     // 80B pitch
    __shared__ __half sB[2][BN][40];

    const int tid  = threadIdx.x;
    const int wid  = tid >> 5;
    const int lane = tid & 31;
    const int m0 = blockIdx.x * BM;      // 80 m-blocks (16 Q, 64 K)
    const int n0 = blockIdx.y * BN;      // 4 n-blocks
    const bool isQ = (m0 < BB * QN);
    const float* A = isQ ? (queries + (size_t)m0 * DD)
                         : (keys + (size_t)(m0 - BB * QN) * DD);
    const int off = isQ ? 0 : DD;

    const int wm = (wid & 3) * 16;       // 0..48
    const int wn = (wid >> 2) * 32;      // 0 / 32

    const int arow = tid >> 3;           // 0..31
    const int ac4  = tid & 7;

    float4 pa[2], pb[2];

    #define GLOAD(s) do {                                                       \
        const float* a0 = A + (s) * BK + ac4 * 4;                               \
        pa[0] = *(const float4*)(a0 + (size_t)(arow      ) * DD);               \
        pa[1] = *(const float4*)(a0 + (size_t)(arow + 32 ) * DD);               \
        const float* b0 = W_hidden + off + (s) * BK + ac4 * 4;                  \
        pb[0] = *(const float4*)(b0 + (size_t)(n0 + arow     ) * (2 * DD));     \
        pb[1] = *(const float4*)(b0 + (size_t)(n0 + arow + 32) * (2 * DD));     \
    } while (0)

    #define STS(bf) do {                                                        \
        _Pragma("unroll")                                                       \
        for (int i = 0; i < 2; i++) {                                           \
            __half2* p = (__half2*)&sA[bf][arow + i * 32][ac4 * 4];             \
            p[0] = __floats2half2_rn(pa[i].x, pa[i].y);                         \
            p[1] = __floats2half2_rn(pa[i].z, pa[i].w);                         \
        }                                                                       \
        _Pragma("unroll")                                                       \
        for (int i = 0; i < 2; i++) {                                           \
            __half2* p = (__half2*)&sB[bf][arow + i * 32][ac4 * 4];             \
            p[0] = __floats2half2_rn(pb[i].x, pb[i].y);                         \
            p[1] = __floats2half2_rn(pb[i].z, pb[i].w);                         \
        }                                                                       \
    } while (0)

    float c[4][4] = {};

    GLOAD(0);
    STS(0);
    __syncthreads();

    const int la15 = lane & 15, la7 = lane & 7;
    const int akoff = (lane >> 4) * 8;
    const int bneff = la7 + ((lane >> 4) << 3);
    const int bkoff = ((lane >> 3) & 1) * 8;

    #pragma unroll
    for (int s = 0; s < DD / BK; s++) {
        const int buf = s & 1;
        if (s + 1 < DD / BK) GLOAD(s + 1);

        #pragma unroll
        for (int k16 = 0; k16 < BK; k16 += 16) {
            unsigned int a[4], b[2][4];
            {
                unsigned int addr = (unsigned int)__cvta_generic_to_shared(
                    &sA[buf][wm + la15][k16 + akoff]);
                ldsm4(a[0], a[1], a[2], a[3], addr);
            }
            #pragma unroll
            for (int ng = 0; ng < 2; ng++) {
                unsigned int addr = (unsigned int)__cvta_generic_to_shared(
                    &sB[buf][wn + ng * 16 + bneff][k16 + bkoff]);
                ldsm4(b[ng][0], b[ng][1], b[ng][2], b[ng][3], addr);
            }
            #pragma unroll
            for (int ng = 0; ng < 2; ng++) {
                mma16816(c[ng * 2 + 0], a[0], a[1], a[2], a[3], b[ng][0], b[ng][1]);
                mma16816(c[ng * 2 + 1], a[0], a[1], a[2], a[3], b[ng][2], b[ng][3]);
            }
        }

        if (s + 1 < DD / BK) {
            STS((s + 1) & 1);
            __syncthreads();
        }
    }
    __syncthreads();

    __half (*cs)[72] = (__half(*)[72])&sA[0][0][0];
    {
        int r0 = wm + (lane >> 2);
        int colb = (lane & 3) * 2;
        #pragma unroll
        for (int nf = 0; nf < 4; nf++) {
            int col = wn + nf * 8 + colb;
            *(__half2*)&cs[r0][col]     = __floats2half2_rn(c[nf][0], c[nf][1]);
            *(__half2*)&cs[r0 + 8][col] = __floats2half2_rn(c[nf][2], c[nf][3]);
        }
    }
    __syncthreads();

    if (isQ) {
        #pragma unroll
        for (int i = 0; i < 2; i++) {
            int id = tid + i * 256;
            int row = id >> 3, seg = id & 7;
            *(uint4*)&g_qproj[(size_t)(m0 + row) * DD + n0 + seg * 8] =
                *(const uint4*)&cs[row][seg * 8];
        }
    } else {
        #pragma unroll
        for (int i = 0; i < 2; i++) {
            int id = tid + i * 256;
            int cc = id >> 6, krow = id & 63;
            int krg = m0 - BB * QN + krow;
            int b = krg >> 9, k = krg & (KN - 1);
            *(uint4*)&g_kprojT[(size_t)(((b * 32 + (n0 >> 3) + cc) * KN) + k) * 8] =
                *(const uint4*)&cs[krow][cc * 8];
        }
    }
    #undef GLOAD
    #undef STS
}

// ---------------------------------------------------------------------------
// Kernel 2 (fused): logits + softmax + output GEMV.
// Block = (b, 4 queries), 512 threads (one k per thread), occupancy 1
// (128 regs) with an explicit register prefetch pipeline on the kv loads.
// ---------------------------------------------------------------------------
__global__ __launch_bounds__(512, 1) void attn_kernel(
    const float* __restrict__ values,
    const void* __restrict__ valid_len,
    const float* __restrict__ W_score,
    float* __restrict__ out)
{
    __shared__ uint4 qpu[4][32];           // 4 queries x 256 halves
    __shared__ unsigned int wsh[DD / 2];   // W_score packed half2
    __shared__ float sl[4][KN];
    __shared__ float red_m[16];
    __shared__ float red_s[16];

    const int tid = threadIdx.x;
    const int b  = blockIdx.x >> 5;
    const int q0 = (blockIdx.x & 31) * 4;

    if (tid < 128)
        wsh[tid] = packf2(*(const float2*)&W_score[tid * 2]);
    else if (tid < 256) {
        int t = tid - 128;
        int j = t >> 5, c = t & 31;
        qpu[j][c] = ((const uint4*)(g_qproj + (size_t)(b * QN + q0 + j) * DD))[c];
    }

    int vl;
    {
        const int* w32 = (const int*)valid_len;
        bool is64 = ((w32[1] | w32[3] | w32[5] | w32[7]) == 0);
        vl = is64 ? (int)(((const long long*)valid_len)[b]) : w32[b];
    }
    __syncthreads();

    // ---- logits: one k per thread; explicit prefetch software pipeline ----
    {
        const int k = tid;
        const bool valid = (k < vl);
        float acc[4] = {};
        if (valid) {
            const uint4* kp = (const uint4*)g_kprojT + (b * 32) * KN + k;
            uint4 kv0 = kp[0], kv1 = kp[KN], kv2 = kp[2 * KN], kv3 = kp[3 * KN];
            #pragma unroll 1
            for (int c = 0; c < 32; c += 4) {
                uint4 nk0, nk1, nk2, nk3;
                if (c + 4 < 32) {
                    const uint4* np = kp + (c + 4) * KN;
                    nk0 = np[0]; nk1 = np[KN]; nk2 = np[2 * KN]; nk3 = np[3 * KN];
                }
                uint4 wv0 = *(const uint4*)&wsh[c * 4];
                uint4 wv1 = *(const uint4*)&wsh[c * 4 + 4];
                uint4 wv2 = *(const uint4*)&wsh[c * 4 + 8];
                uint4 wv3 = *(const uint4*)&wsh[c * 4 + 12];
                #pragma unroll
                for (int j = 0; j < 4; j++) {
                    // pair (c, c+1) — association identical to R15
                    {
                        uint4 qv0 = qpu[j][c];
                        uint4 qv1 = qpu[j][c + 1];
                        unsigned int h0, h1;
                        h0 = hfma2u(htanh2(hadd2u(qv0.x, kv0.x)), wv0.x, 0u);
                        h1 = hfma2u(htanh2(hadd2u(qv0.y, kv0.y)), wv0.y, 0u);
                        h0 = hfma2u(htanh2(hadd2u(qv0.z, kv0.z)), wv0.z, h0);
                        h1 = hfma2u(htanh2(hadd2u(qv0.w, kv0.w)), wv0.w, h1);
                        h0 = hfma2u(htanh2(hadd2u(qv1.x, kv1.x)), wv1.x, h0);
                        h1 = hfma2u(htanh2(hadd2u(qv1.y, kv1.y)), wv1.y, h1);
                        h0 = hfma2u(htanh2(hadd2u(qv1.z, kv1.z)), wv1.z, h0);
                        h1 = hfma2u(htanh2(hadd2u(qv1.w, kv1.w)), wv1.w, h1);
                        unsigned int hs = hadd2u(h0, h1);
                        float2 f = __half22float2(*(__half2*)&hs);
                        acc[j] += f.x + f.y;
                    }
                    // pair (c+2, c+3)
                    {
                        uint4 qv0 = qpu[j][c + 2];
                        uint4 qv1 = qpu[j][c + 3];
                        unsigned int h0, h1;
                        h0 = hfma2u(htanh2(hadd2u(qv0.x, kv2.x)), wv2.x, 0u);
                        h1 = hfma2u(htanh2(hadd2u(qv0.y, kv2.y)), wv2.y, 0u);
                        h0 = hfma2u(htanh2(hadd2u(qv0.z, kv2.z)), wv2.z, h0);
                        h1 = hfma2u(htanh2(hadd2u(qv0.w, kv2.w)), wv2.w, h1);
                        h0 = hfma2u(htanh2(hadd2u(qv1.x, kv3.x)), wv3.x, h0);
                        h1 = hfma2u(htanh2(hadd2u(qv1.y, kv3.y)), wv3.y, h1);
                        h0 = hfma2u(htanh2(hadd2u(qv1.z, kv3.z)), wv3.z, h0);
                        h1 = hfma2u(htanh2(hadd2u(qv1.w, kv3.w)), wv3.w, h1);
                        unsigned int hs = hadd2u(h0, h1);
                        float2 f = __half22float2(*(__half2*)&hs);
                        acc[j] += f.x + f.y;
                    }
                }
                kv0 = nk0; kv1 = nk1; kv2 = nk2; kv3 = nk3;
            }
        }
        #pragma unroll
        for (int j = 0; j < 4; j++)
            sl[j][k] = valid ? acc[j] : NEGC;
    }
    __syncthreads();

    // ---- softmax, all 4 queries in parallel (128 threads per query) ----
    {
        const int g = tid >> 7;          // query index
        const int t = tid & 127;
        const int w = t >> 5;            // warp within group

        float v0 = sl[g][t];
        float v1 = sl[g][t + 128];
        float v2 = sl[g][t + 256];
        float v3 = sl[g][t + 384];

        float m = fmaxf(fmaxf(v0, v1), fmaxf(v2, v3));
        #pragma unroll
        for (int o = 16; o; o >>= 1)
            m = fmaxf(m, __shfl_xor_sync(0xFFFFFFFFu, m, o));
        if ((t & 31) == 0) red_m[g * 4 + w] = m;
        __syncthreads();
        m = fmaxf(fmaxf(red_m[g * 4], red_m[g * 4 + 1]),
                  fmaxf(red_m[g * 4 + 2], red_m[g * 4 + 3]));

        float e0 = __expf(v0 - m);
        float e1 = __expf(v1 - m);
        float e2 = __expf(v2 - m);
        float e3 = __expf(v3 - m);
        float s = (e0 + e1) + (e2 + e3);
        #pragma unroll
        for (int o = 16; o; o >>= 1)
            s += __shfl_xor_sync(0xFFFFFFFFu, s, o);
        if ((t & 31) == 0) red_s[g * 4 + w] = s;
        __syncthreads();
        float inv = 1.0f / (((red_s[g * 4] + red_s[g * 4 + 1]) +
                             (red_s[g * 4 + 2] + red_s[g * 4 + 3])));

        sl[g][t]       = e0 * inv;
        sl[g][t + 128] = e1 * inv;
        sl[g][t + 256] = e2 * inv;
        sl[g][t + 384] = e3 * inv;
    }
    __syncthreads();

    // ---- output GEMV: thread owns (query pair, channel); skip zero probs ----
    {
        const int qs = (tid >> 8) * 2;   // 0 or 2
        const int v  = tid & 255;
        const int kmax = (vl == 0) ? (KN / 4) : ((vl + 3) >> 2);
        const float* vptr = values + (size_t)b * KN * DD + v;
        float a0 = 0.f, a1 = 0.f;
        #pragma unroll 4
        for (int k4 = 0; k4 < kmax; k4++) {
            float w0[4], w1[4];
            *(float4*)w0 = *(const float4*)&sl[qs][k4 * 4];
            *(float4*)w1 = *(const float4*)&sl[qs + 1][k4 * 4];
            #pragma unroll
            for (int p = 0; p < 4; p++) {
                float vv = vptr[(size_t)(k4 * 4 + p) * DD];
                a0 = fmaf(w0[p], vv, a0);
                a1 = fmaf(w1[p], vv, a1);
            }
        }
        out[(size_t)(b * QN + q0 + qs    ) * DD + v] = a0;
        out[(size_t)(b * QN + q0 + qs + 1) * DD + v] = a1;
    }
}

extern "C" void kernel_launch(void* const* d_in, const int* in_sizes, int n_in,
                              void* d_out, int out_size)
{
    const float* keys     = (const float*)d_in[0];
    const float* values   = (const float*)d_in[1];
    const float* queries  = (const float*)d_in[2];
    const void*  valid    = d_in[3];
    const float* W_hidden = (const float*)d_in[4];
    const float* W_score  = (const float*)d_in[5];
    float* out = (float*)d_out;

    proj_kernel<<<dim3(80, 4), 256>>>(queries, keys, W_hidden);
    attn_kernel<<<BB * (QN / 4), 512>>>(values, valid, W_score, out);
}

// round 17
// speedup vs baseline: 1.0688x; 1.0688x over previous
#include <cuda_runtime.h>
#include <cuda_bf16.h>
#include <cuda_fp16.h>
#include <cstdint>

#define BB 8
#define KN 512
#define QN 128
#define DD 256
#define NEGC (-1000000.0f)

#define BM 64
#define BN 64
#define BK 32

// scratch
__device__ __half g_qproj[BB * QN * DD];                 // [b*128+q][h]     512KB
__device__ __half g_kprojT[BB * (DD / 8) * KN * 8];      // [b][h/8][k][h%8]   2MB

__device__ __forceinline__ unsigned int htanh2(unsigned int x) {
    unsigned int y;
    asm("tanh.approx.f16x2 %0, %1;" : "=r"(y) : "r"(x));
    return y;
}
__device__ __forceinline__ unsigned int hadd2u(unsigned int a, unsigned int b) {
    unsigned int r;
    asm("add.f16x2 %0, %1, %2;" : "=r"(r) : "r"(a), "r"(b));
    return r;
}
__device__ __forceinline__ unsigned int hfma2u(unsigned int a, unsigned int b, unsigned int c) {
    unsigned int r;
    asm("fma.rn.f16x2 %0, %1, %2, %3;" : "=r"(r) : "r"(a), "r"(b), "r"(c));
    return r;
}
__device__ __forceinline__ unsigned int packf2(float2 v) {
    __half2 h = __floats2half2_rn(v.x, v.y);
    return *(unsigned int*)&h;
}
__device__ __forceinline__ void mma16816(float c[4],
    unsigned int a0, unsigned int a1, unsigned int a2, unsigned int a3,
    unsigned int b0, unsigned int b1)
{
    asm("mma.sync.aligned.m16n8k16.row.col.f32.f16.f16.f32 "
        "{%0,%1,%2,%3}, {%4,%5,%6,%7}, {%8,%9}, {%0,%1,%2,%3};"
        : "+f"(c[0]), "+f"(c[1]), "+f"(c[2]), "+f"(c[3])
        : "r"(a0), "r"(a1), "r"(a2), "r"(a3), "r"(b0), "r"(b1));
}
__device__ __forceinline__ void ldsm4(unsigned int& r0, unsigned int& r1,
                                      unsigned int& r2, unsigned int& r3,
                                      unsigned int addr)
{
    asm volatile("ldmatrix.sync.aligned.m8n8.x4.shared.b16 {%0,%1,%2,%3}, [%4];"
        : "=r"(r0), "=r"(r1), "=r"(r2), "=r"(r3) : "r"(addr));
}

// ---------------------------------------------------------------------------
// Kernel 1: projection GEMM, smem-staged tensor-core pipeline. (unchanged)
// ---------------------------------------------------------------------------
__global__ __launch_bounds__(256) void proj_kernel(
    const float* __restrict__ queries,
    const float* __restrict__ keys,
    const float* __restrict__ W_hidden)
{
    __shared__ __half sA[2][BM][40];     // 80B pitch
    __shared__ __half sB[2][BN][40];

    const int tid  = threadIdx.x;
    const int wid  = tid >> 5;
    const int lane = tid & 31;
    const int m0 = blockIdx.x * BM;      // 80 m-blocks (16 Q, 64 K)
    const int n0 = blockIdx.y * BN;      // 4 n-blocks
    const bool isQ = (m0 < BB * QN);
    const float* A = isQ ? (queries + (size_t)m0 * DD)
                         : (keys + (size_t)(m0 - BB * QN) * DD);
    const int off = isQ ? 0 : DD;

    const int wm = (wid & 3) * 16;       // 0..48
    const int wn = (wid >> 2) * 32;      // 0 / 32

    const int arow = tid >> 3;           // 0..31
    const int ac4  = tid & 7;

    float4 pa[2], pb[2];

    #define GLOAD(s) do {                                                       \
        const float* a0 = A + (s) * BK + ac4 * 4;                               \
        pa[0] = *(const float4*)(a0 + (size_t)(arow      ) * DD);               \
        pa[1] = *(const float4*)(a0 + (size_t)(arow + 32 ) * DD);               \
        const float* b0 = W_hidden + off + (s) * BK + ac4 * 4;                  \
        pb[0] = *(const float4*)(b0 + (size_t)(n0 + arow     ) * (2 * DD));     \
        pb[1] = *(const float4*)(b0 + (size_t)(n0 + arow + 32) * (2 * DD));     \
    } while (0)

    #define STS(bf) do {                                                        \
        _Pragma("unroll")                                                       \
        for (int i = 0; i < 2; i++) {                                           \
            __half2* p = (__half2*)&sA[bf][arow + i * 32][ac4 * 4];             \
            p[0] = __floats2half2_rn(pa[i].x, pa[i].y);                         \
            p[1] = __floats2half2_rn(pa[i].z, pa[i].w);                         \
        }                                                                       \
        _Pragma("unroll")                                                       \
        for (int i = 0; i < 2; i++) {                                           \
            __half2* p = (__half2*)&sB[bf][arow + i * 32][ac4 * 4];             \
            p[0] = __floats2half2_rn(pb[i].x, pb[i].y);                         \
            p[1] = __floats2half2_rn(pb[i].z, pb[i].w);                         \
        }                                                                       \
    } while (0)

    float c[4][4] = {};

    GLOAD(0);
    STS(0);
    __syncthreads();

    const int la15 = lane & 15, la7 = lane & 7;
    const int akoff = (lane >> 4) * 8;
    const int bneff = la7 + ((lane >> 4) << 3);
    const int bkoff = ((lane >> 3) & 1) * 8;

    #pragma unroll
    for (int s = 0; s < DD / BK; s++) {
        const int buf = s & 1;
        if (s + 1 < DD / BK) GLOAD(s + 1);

        #pragma unroll
        for (int k16 = 0; k16 < BK; k16 += 16) {
            unsigned int a[4], b[2][4];
            {
                unsigned int addr = (unsigned int)__cvta_generic_to_shared(
                    &sA[buf][wm + la15][k16 + akoff]);
                ldsm4(a[0], a[1], a[2], a[3], addr);
            }
            #pragma unroll
            for (int ng = 0; ng < 2; ng++) {
                unsigned int addr = (unsigned int)__cvta_generic_to_shared(
                    &sB[buf][wn + ng * 16 + bneff][k16 + bkoff]);
                ldsm4(b[ng][0], b[ng][1], b[ng][2], b[ng][3], addr);
            }
            #pragma unroll
            for (int ng = 0; ng < 2; ng++) {
                mma16816(c[ng * 2 + 0], a[0], a[1], a[2], a[3], b[ng][0], b[ng][1]);
                mma16816(c[ng * 2 + 1], a[0], a[1], a[2], a[3], b[ng][2], b[ng][3]);
            }
        }

        if (s + 1 < DD / BK) {
            STS((s + 1) & 1);
            __syncthreads();
        }
    }
    __syncthreads();

    __half (*cs)[72] = (__half(*)[72])&sA[0][0][0];
    {
        int r0 = wm + (lane >> 2);
        int colb = (lane & 3) * 2;
        #pragma unroll
        for (int nf = 0; nf < 4; nf++) {
            int col = wn + nf * 8 + colb;
            *(__half2*)&cs[r0][col]     = __floats2half2_rn(c[nf][0], c[nf][1]);
            *(__half2*)&cs[r0 + 8][col] = __floats2half2_rn(c[nf][2], c[nf][3]);
        }
    }
    __syncthreads();

    if (isQ) {
        #pragma unroll
        for (int i = 0; i < 2; i++) {
            int id = tid + i * 256;
            int row = id >> 3, seg = id & 7;
            *(uint4*)&g_qproj[(size_t)(m0 + row) * DD + n0 + seg * 8] =
                *(const uint4*)&cs[row][seg * 8];
        }
    } else {
        #pragma unroll
        for (int i = 0; i < 2; i++) {
            int id = tid + i * 256;
            int cc = id >> 6, krow = id & 63;
            int krg = m0 - BB * QN + krow;
            int b = krg >> 9, k = krg & (KN - 1);
            *(uint4*)&g_kprojT[(size_t)(((b * 32 + (n0 >> 3) + cc) * KN) + k) * 8] =
                *(const uint4*)&cs[krow][cc * 8];
        }
    }
    #undef GLOAD
    #undef STS
}

// ---------------------------------------------------------------------------
// Kernel 2 (fused): logits + softmax + output GEMV.
// Block = (b, 2 queries), 512 threads, one k per thread.
// b = bid & 7 (batch-interleaved for SM load balance), grid 512 (~1.7 waves).
// ---------------------------------------------------------------------------
__global__ __launch_bounds__(512, 2) void attn_kernel(
    const float* __restrict__ values,
    const void* __restrict__ valid_len,
    const float* __restrict__ W_score,
    float* __restrict__ out)
{
    __shared__ uint4 qpu[2][32];           // 2 queries x 256 halves
    __shared__ unsigned int wsh[DD / 2];   // W_score packed half2
    __shared__ float sl[2][KN];
    __shared__ float red_m[16];
    __shared__ float red_s[16];

    const int tid = threadIdx.x;
    const int b  = blockIdx.x & 7;         // batch-interleaved
    const int q0 = (blockIdx.x >> 3) * 2;

    if (tid < 128)
        wsh[tid] = packf2(*(const float2*)&W_score[tid * 2]);
    else if (tid < 192) {
        int t = tid - 128;
        int j = t >> 5, c = t & 31;
        qpu[j][c] = ((const uint4*)(g_qproj + (size_t)(b * QN + q0 + j) * DD))[c];
    }

    int vl;
    {
        const int* w32 = (const int*)valid_len;
        bool is64 = ((w32[1] | w32[3] | w32[5] | w32[7]) == 0);
        vl = is64 ? (int)(((const long long*)valid_len)[b]) : w32[b];
    }
    __syncthreads();

    // ---- logits: one k per thread; masked threads skip the loop ----
    {
        const int k = tid;
        const bool valid = (k < vl);
        float acc[2] = {};
        if (valid) {
            const uint4* kp = (const uint4*)g_kprojT + (b * 32) * KN + k;
            for (int c = 0; c < 32; c += 4) {
                uint4 kv0 = kp[(c    ) * KN];
                uint4 kv1 = kp[(c + 1) * KN];
                uint4 kv2 = kp[(c + 2) * KN];
                uint4 kv3 = kp[(c + 3) * KN];
                uint4 wv0 = *(const uint4*)&wsh[c * 4];
                uint4 wv1 = *(const uint4*)&wsh[c * 4 + 4];
                uint4 wv2 = *(const uint4*)&wsh[c * 4 + 8];
                uint4 wv3 = *(const uint4*)&wsh[c * 4 + 12];
                #pragma unroll
                for (int j = 0; j < 2; j++) {
                    // pair (c, c+1) — per-(q,k) association identical to R15
                    {
                        uint4 qv0 = qpu[j][c];
                        uint4 qv1 = qpu[j][c + 1];
                        unsigned int h0, h1;
                        h0 = hfma2u(htanh2(hadd2u(qv0.x, kv0.x)), wv0.x, 0u);
                        h1 = hfma2u(htanh2(hadd2u(qv0.y, kv0.y)), wv0.y, 0u);
                        h0 = hfma2u(htanh2(hadd2u(qv0.z, kv0.z)), wv0.z, h0);
                        h1 = hfma2u(htanh2(hadd2u(qv0.w, kv0.w)), wv0.w, h1);
                        h0 = hfma2u(htanh2(hadd2u(qv1.x, kv1.x)), wv1.x, h0);
                        h1 = hfma2u(htanh2(hadd2u(qv1.y, kv1.y)), wv1.y, h1);
                        h0 = hfma2u(htanh2(hadd2u(qv1.z, kv1.z)), wv1.z, h0);
                        h1 = hfma2u(htanh2(hadd2u(qv1.w, kv1.w)), wv1.w, h1);
                        unsigned int hs = hadd2u(h0, h1);
                        float2 f = __half22float2(*(__half2*)&hs);
                        acc[j] += f.x + f.y;
                    }
                    // pair (c+2, c+3)
                    {
                        uint4 qv0 = qpu[j][c + 2];
                        uint4 qv1 = qpu[j][c + 3];
                        unsigned int h0, h1;
                        h0 = hfma2u(htanh2(hadd2u(qv0.x, kv2.x)), wv2.x, 0u);
                        h1 = hfma2u(htanh2(hadd2u(qv0.y, kv2.y)), wv2.y, 0u);
                        h0 = hfma2u(htanh2(hadd2u(qv0.z, kv2.z)), wv2.z, h0);
                        h1 = hfma2u(htanh2(hadd2u(qv0.w, kv2.w)), wv2.w, h1);
                        h0 = hfma2u(htanh2(hadd2u(qv1.x, kv3.x)), wv3.x, h0);
                        h1 = hfma2u(htanh2(hadd2u(qv1.y, kv3.y)), wv3.y, h1);
                        h0 = hfma2u(htanh2(hadd2u(qv1.z, kv3.z)), wv3.z, h0);
                        h1 = hfma2u(htanh2(hadd2u(qv1.w, kv3.w)), wv3.w, h1);
                        unsigned int hs = hadd2u(h0, h1);
                        float2 f = __half22float2(*(__half2*)&hs);
                        acc[j] += f.x + f.y;
                    }
                }
            }
        }
        #pragma unroll
        for (int j = 0; j < 2; j++)
            sl[j][k] = valid ? acc[j] : NEGC;
    }
    __syncthreads();

    // ---- softmax, both queries in parallel (256 threads per query) ----
    {
        const int g = tid >> 8;          // query index (0/1)
        const int t = tid & 255;
        const int w = t >> 5;            // warp within group (0..7)

        float v0 = sl[g][t];
        float v1 = sl[g][t + 256];

        float m = fmaxf(v0, v1);
        #pragma unroll
        for (int o = 16; o; o >>= 1)
            m = fmaxf(m, __shfl_xor_sync(0xFFFFFFFFu, m, o));
        if ((t & 31) == 0) red_m[g * 8 + w] = m;
        __syncthreads();
        m = red_m[g * 8];
        #pragma unroll
        for (int i = 1; i < 8; i++) m = fmaxf(m, red_m[g * 8 + i]);

        float e0 = __expf(v0 - m);
        float e1 = __expf(v1 - m);
        float s = e0 + e1;
        #pragma unroll
        for (int o = 16; o; o >>= 1)
            s += __shfl_xor_sync(0xFFFFFFFFu, s, o);
        if ((t & 31) == 0) red_s[g * 8 + w] = s;
        __syncthreads();
        float ss = red_s[g * 8];
        #pragma unroll
        for (int i = 1; i < 8; i++) ss += red_s[g * 8 + i];
        float inv = 1.0f / ss;

        sl[g][t]       = e0 * inv;
        sl[g][t + 256] = e1 * inv;
    }
    __syncthreads();

    // ---- output GEMV: thread owns (query, channel); skip zero probs ----
    {
        const int qs = tid >> 8;         // 0 or 1
        const int v  = tid & 255;
        const int kmax = (vl == 0) ? (KN / 4) : ((vl + 3) >> 2);
        const float* vptr = values + (size_t)b * KN * DD + v;
        float a0 = 0.f;
        #pragma unroll 4
        for (int k4 = 0; k4 < kmax; k4++) {
            float w0[4];
            *(float4*)w0 = *(const float4*)&sl[qs][k4 * 4];
            #pragma unroll
            for (int p = 0; p < 4; p++) {
                float vv = vptr[(size_t)(k4 * 4 + p) * DD];
                a0 = fmaf(w0[p], vv, a0);
            }
        }
        out[(size_t)(b * QN + q0 + qs) * DD + v] = a0;
    }
}

extern "C" void kernel_launch(void* const* d_in, const int* in_sizes, int n_in,
                              void* d_out, int out_size)
{
    const float* keys     = (const float*)d_in[0];
    const float* values   = (const float*)d_in[1];
    const float* queries  = (const float*)d_in[2];
    const void*  valid    = d_in[3];
    const float* W_hidden = (const float*)d_in[4];
    const float* W_score  = (const float*)d_in[5];
    float* out = (float*)d_out;

    proj_kernel<<<dim3(80, 4), 256>>>(queries, keys, W_hidden);
    attn_kernel<<<BB * (QN / 2), 512>>>(values, valid, W_score, out);
}